// round 2
// baseline (speedup 1.0000x reference)
#include <cuda_runtime.h>
#include <cstdint>

// ---------------------------------------------------------------------------
// CSAA module: resize(1x1 conv) -> width axial attn -> height axial attn ->
// restore(1x1 conv).  B=8, CIN=256, COUT=256, R=H=W=128.
// All GEMMs are 128-sized; implemented as smem-tiled fp32 kernels using
// Blackwell packed fma.rn.f32x2 (2x fp32 FMA throughput vs scalar FFMA).
// ---------------------------------------------------------------------------

#define TPB 256
#define PAD 130                       // even (8B-aligned pairs), 130%32==2 -> <=2-way conflicts on transpose fills
#define TILE_F (128 * PAD)
#define SMEM_BYTES (2 * TILE_F * (int)sizeof(float))

// Scratch (allocation-free rule: __device__ globals). 4 x 64 MB.
__device__ float g_b0[16777216];      // X / outw / out2
__device__ float g_b1[16777216];      // q / q2 / hat
__device__ float g_b2[16777216];      // k / k2
__device__ float g_b3[16777216];      // v / v2

// ---- smem tile loaders -----------------------------------------------------
// Ss layout: Ss[k*PAD + n], k = contraction index (0..127), n = free index.

__device__ __forceinline__ void load_direct(float* __restrict__ Ss,
                                            const float* __restrict__ g,
                                            int gstride, int tid) {
  // global tile g[k][n] (row k contiguous in n)
  for (int t = tid; t < 16384; t += TPB) {
    int k = t >> 7, n = t & 127;
    Ss[k * PAD + n] = g[(size_t)k * gstride + n];
  }
}

__device__ __forceinline__ void load_T(float* __restrict__ Ss,
                                       const float* __restrict__ g,
                                       int gstride, int tid) {
  // global tile g[m][k] (row m contiguous in k) -> Ss[k][m]
  for (int t = tid; t < 16384; t += TPB) {
    int m = t >> 7, k = t & 127;
    Ss[k * PAD + m] = g[(size_t)m * gstride + k];
  }
}

// ---- 128x128x128 register-tiled GEMM core ---------------------------------
// C[m][n] = sum_k As[k][m] * Bs[k][n]
// thread (tx,ty), tx=tid&15, ty=tid>>4. Thread owns rows m = i*16+ty (i<8),
// col pairs n = j*32 + tx*2 (+1) (j<4). Accumulators are f32x2 pairs.

__device__ __forceinline__ void zero_acc(unsigned long long acc[8][4]) {
#pragma unroll
  for (int i = 0; i < 8; ++i)
#pragma unroll
    for (int j = 0; j < 4; ++j) acc[i][j] = 0ull;
}

__device__ __forceinline__ void gemm128(const float* __restrict__ As,
                                        const float* __restrict__ Bs,
                                        unsigned long long acc[8][4],
                                        int tx, int ty) {
#pragma unroll 4
  for (int k = 0; k < 128; ++k) {
    const float* br = Bs + k * PAD + tx * 2;
    unsigned long long bp[4];
#pragma unroll
    for (int j = 0; j < 4; ++j)
      bp[j] = *reinterpret_cast<const unsigned long long*>(br + j * 32);
    const float* ar = As + k * PAD + ty;
    unsigned long long ap[8];
#pragma unroll
    for (int i = 0; i < 8; ++i) {
      float a = ar[i * 16];
      asm("mov.b64 %0, {%1, %1};" : "=l"(ap[i]) : "f"(a));
    }
#pragma unroll
    for (int i = 0; i < 8; ++i)
#pragma unroll
      for (int j = 0; j < 4; ++j)
        asm("fma.rn.f32x2 %0, %1, %2, %0;"
            : "+l"(acc[i][j]) : "l"(ap[i]), "l"(bp[j]));
  }
}

__device__ __forceinline__ void store_tile(float* __restrict__ out, int rowStride,
                                           const float* __restrict__ bias, int biasBase,
                                           unsigned long long acc[8][4],
                                           int tx, int ty) {
#pragma unroll
  for (int i = 0; i < 8; ++i) {
    int row = i * 16 + ty;
    float bv = bias ? bias[biasBase + row] : 0.0f;
#pragma unroll
    for (int j = 0; j < 4; ++j) {
      float lo, hi;
      asm("mov.b64 {%0, %1}, %2;" : "=f"(lo), "=f"(hi) : "l"(acc[i][j]));
      float2 v = make_float2(lo + bv, hi + bv);
      *reinterpret_cast<float2*>(out + (size_t)row * rowStride + j * 32 + tx * 2) = v;
    }
  }
}

// ---- kernel 1: resize 1x1 conv  X[b,o,p] = Wr[o,:]·x[b,:,p] + br ----------
__global__ void __launch_bounds__(TPB)
resize_kernel(const float* __restrict__ x, const float* __restrict__ Wr,
              const float* __restrict__ br) {
  extern __shared__ float sm[];
  float* As = sm;
  float* Bs = sm + TILE_F;
  int tid = threadIdx.x, tx = tid & 15, ty = tid >> 4;
  int pt = blockIdx.x, b = blockIdx.y;
  size_t p0 = (size_t)pt * 128;

  unsigned long long acc[8][4];
  zero_acc(acc);
  for (int cc = 0; cc < 2; ++cc) {
    __syncthreads();
    load_T(As, Wr + cc * 128, 256, tid);                       // Wr[o][cc*128+k] -> As[k][o]
    load_direct(Bs, x + (size_t)b * 4194304 + (size_t)cc * 128 * 16384 + p0,
                16384, tid);                                   // x[b][c][p]
    __syncthreads();
    gemm128(As, Bs, acc, tx, ty);
  }
  store_tile(g_b0 + (size_t)b * 2097152 + p0, 16384, br, 0, acc, tx, ty);
}

// ---- kernel 2/4: qkv projections ------------------------------------------
// width (tB=0): per (b,r) slice X[b,r,h,w], contraction over h (Bs direct)
//   q[b,o,r,w] = sum_h Wq[o,h] X[b,r,h,w]
// height (tB=1): per (b,c) slice M[h,w] = outw[b,h,c,w], contraction over w
//   q2[b,o,c,h] = sum_w Wq[o,w] M[h,w]   (Bs = M^T)
__global__ void __launch_bounds__(TPB)
qkv_kernel(const float* __restrict__ Wq, const float* __restrict__ bq,
           const float* __restrict__ Wk, const float* __restrict__ bk,
           const float* __restrict__ Wv, const float* __restrict__ bv,
           int tB) {
  extern __shared__ float sm[];
  float* As = sm;
  float* Bs = sm + TILE_F;
  int tid = threadIdx.x, tx = tid & 15, ty = tid >> 4;
  int rr = blockIdx.x, b = blockIdx.y;

  if (!tB)
    load_direct(Bs, g_b0 + (size_t)b * 2097152 + (size_t)rr * 16384, 128, tid);
  else
    load_T(Bs, g_b0 + (size_t)b * 2097152 + (size_t)rr * 128, 16384, tid);

  const float* Ws[3] = {Wq, Wk, Wv};
  const float* bs[3] = {bq, bk, bv};
  float* outs[3] = {g_b1, g_b2, g_b3};
  size_t obase = (size_t)b * 2097152 + (size_t)rr * 128;

  for (int s = 0; s < 3; ++s) {
    __syncthreads();                 // previous gemm done (and Bs fill on s==0)
    load_T(As, Ws[s], 128, tid);     // W[o][k] -> As[k][o]
    __syncthreads();
    unsigned long long acc[8][4];
    zero_acc(acc);
    gemm128(As, Bs, acc, tx, ty);
    store_tile(outs[s] + obase, 16384, bs[s], 0, acc, tx, ty);
  }
}

// ---- kernel 3/5: fused attention per (b,head) -----------------------------
// Q,K,V = g_b1/2/3 [b,o,r,w]; out = g_b0 [b,o,r,w]
// S = softmax_rows(Q K^T); out = S V
__global__ void __launch_bounds__(TPB)
attn_kernel() {
  extern __shared__ float sm[];
  float* As = sm;
  float* Bs = sm + TILE_F;
  int tid = threadIdx.x, tx = tid & 15, ty = tid >> 4;
  int o = blockIdx.x, b = blockIdx.y;
  size_t base = ((size_t)b * 128 + o) * 16384;

  load_T(As, g_b1 + base, 128, tid);   // Q[r][w] -> As[w][r]
  load_T(Bs, g_b2 + base, 128, tid);   // K[u][w] -> Bs[w][u]
  __syncthreads();

  unsigned long long acc[8][4];
  zero_acc(acc);
  gemm128(As, Bs, acc, tx, ty);        // S[r][u]
  __syncthreads();                     // everyone done reading As/Bs

  // row softmax + write P transposed into As: As[u][r]
#pragma unroll
  for (int i = 0; i < 8; ++i) {
    float v[8];
#pragma unroll
    for (int j = 0; j < 4; ++j) {
      float lo, hi;
      asm("mov.b64 {%0, %1}, %2;" : "=f"(lo), "=f"(hi) : "l"(acc[i][j]));
      v[2 * j] = lo; v[2 * j + 1] = hi;
    }
    float mx = v[0];
#pragma unroll
    for (int jj = 1; jj < 8; ++jj) mx = fmaxf(mx, v[jj]);
#pragma unroll
    for (int m = 1; m < 16; m <<= 1)
      mx = fmaxf(mx, __shfl_xor_sync(0xffffffffu, mx, m));
    float s = 0.0f;
#pragma unroll
    for (int jj = 0; jj < 8; ++jj) { v[jj] = __expf(v[jj] - mx); s += v[jj]; }
#pragma unroll
    for (int m = 1; m < 16; m <<= 1)
      s += __shfl_xor_sync(0xffffffffu, s, m);
    float inv = 1.0f / s;
    int r = i * 16 + ty;
#pragma unroll
    for (int jj = 0; jj < 8; ++jj) {
      int u = (jj >> 1) * 32 + tx * 2 + (jj & 1);
      As[u * PAD + r] = v[jj] * inv;
    }
  }
  load_direct(Bs, g_b3 + base, 128, tid);   // V[u][w]
  __syncthreads();

  zero_acc(acc);
  gemm128(As, Bs, acc, tx, ty);             // out[r][w] = P·V
  store_tile(g_b0 + base, 128, nullptr, 0, acc, tx, ty);
}

// ---- kernel 6: transpose out2[b,w,c,h] -> hat[b,c,h,w] --------------------
__global__ void transpose_kernel() {
  __shared__ float tile[32][33];
  int bc = blockIdx.z;
  int b = bc >> 7, c = bc & 127;
  const float* s = g_b0 + ((size_t)b << 21) + ((size_t)c << 7);  // + w*16384 + h
  float* d = g_b1 + ((size_t)b << 21) + ((size_t)c << 14);       // + h*128  + w
  int h0 = blockIdx.x * 32, w0 = blockIdx.y * 32;
  for (int r = threadIdx.y; r < 32; r += 8)
    tile[r][threadIdx.x] = s[(size_t)(w0 + r) * 16384 + h0 + threadIdx.x];
  __syncthreads();
  for (int r = threadIdx.y; r < 32; r += 8)
    d[(size_t)(h0 + r) * 128 + w0 + threadIdx.x] = tile[threadIdx.x][r];
}

// ---- kernel 7: restore 1x1 conv  Y[b,oc,p] = Wo[oc,:]·hat[b,:,p] + bo -----
__global__ void __launch_bounds__(TPB)
restore_kernel(const float* __restrict__ Wo, const float* __restrict__ bo,
               float* __restrict__ out) {
  extern __shared__ float sm[];
  float* As = sm;
  float* Bs = sm + TILE_F;
  int tid = threadIdx.x, tx = tid & 15, ty = tid >> 4;
  int pt = blockIdx.x, mh = blockIdx.y, b = blockIdx.z;
  size_t p0 = (size_t)pt * 128;

  load_T(As, Wo + (size_t)mh * 128 * 128, 128, tid);    // Wo[oc][c] -> As[c][oc]
  load_direct(Bs, g_b1 + (size_t)b * 2097152 + p0, 16384, tid);
  __syncthreads();

  unsigned long long acc[8][4];
  zero_acc(acc);
  gemm128(As, Bs, acc, tx, ty);
  store_tile(out + (size_t)b * 4194304 + (size_t)mh * 128 * 16384 + p0, 16384,
             bo, mh * 128, acc, tx, ty);
}

// ---------------------------------------------------------------------------
extern "C" void kernel_launch(void* const* d_in, const int* in_sizes, int n_in,
                              void* d_out, int out_size) {
  (void)in_sizes; (void)n_in; (void)out_size;
  const float* x   = (const float*)d_in[0];
  const float* Wr  = (const float*)d_in[1];
  const float* br  = (const float*)d_in[2];
  const float* Wqw = (const float*)d_in[3];
  const float* bqw = (const float*)d_in[4];
  const float* Wkw = (const float*)d_in[5];
  const float* bkw = (const float*)d_in[6];
  const float* Wvw = (const float*)d_in[7];
  const float* bvw = (const float*)d_in[8];
  const float* Wqh = (const float*)d_in[9];
  const float* bqh = (const float*)d_in[10];
  const float* Wkh = (const float*)d_in[11];
  const float* bkh = (const float*)d_in[12];
  const float* Wvh = (const float*)d_in[13];
  const float* bvh = (const float*)d_in[14];
  const float* Wo  = (const float*)d_in[15];
  const float* bo  = (const float*)d_in[16];
  float* out = (float*)d_out;

  cudaFuncSetAttribute((const void*)resize_kernel,
                       cudaFuncAttributeMaxDynamicSharedMemorySize, SMEM_BYTES);
  cudaFuncSetAttribute((const void*)qkv_kernel,
                       cudaFuncAttributeMaxDynamicSharedMemorySize, SMEM_BYTES);
  cudaFuncSetAttribute((const void*)attn_kernel,
                       cudaFuncAttributeMaxDynamicSharedMemorySize, SMEM_BYTES);
  cudaFuncSetAttribute((const void*)restore_kernel,
                       cudaFuncAttributeMaxDynamicSharedMemorySize, SMEM_BYTES);

  resize_kernel<<<dim3(128, 8), TPB, SMEM_BYTES>>>(x, Wr, br);
  qkv_kernel<<<dim3(128, 8), TPB, SMEM_BYTES>>>(Wqw, bqw, Wkw, bkw, Wvw, bvw, 0);
  attn_kernel<<<dim3(128, 8), TPB, SMEM_BYTES>>>();
  qkv_kernel<<<dim3(128, 8), TPB, SMEM_BYTES>>>(Wqh, bqh, Wkh, bkh, Wvh, bvh, 1);
  attn_kernel<<<dim3(128, 8), TPB, SMEM_BYTES>>>();
  transpose_kernel<<<dim3(4, 4, 1024), dim3(32, 8)>>>();
  restore_kernel<<<dim3(128, 2, 8), TPB, SMEM_BYTES>>>(Wo, bo, out);
}

// round 3
// speedup vs baseline: 3.2180x; 3.2180x over previous
#include <cuda_runtime.h>
#include <cuda_bf16.h>
#include <cstdint>

// ---------------------------------------------------------------------------
// CSAA: resize(1x1) -> width axial attn -> height axial attn -> restore(1x1).
// B=8, CIN=COUT=256, R=H=W=128. All GEMMs are 128x128x128 tiles on tensor
// cores: mma.sync.m16n8k16 bf16 with 2-way bf16 split (3 MMAs) for fp32-grade
// accuracy. Smem tiles use a 16B-granule XOR swizzle; fragments via ldmatrix.
// ---------------------------------------------------------------------------

#define TPB 256
#define OFF_AH 0u
#define OFF_AL 32768u
#define OFF_BH 65536u
#define OFF_BL 98304u
#define SMEMB 131072

// Scratch (__device__ globals; no allocs allowed).
__device__ float g_b0[16777216];
__device__ float g_b1[16777216];
__device__ float g_b2[16777216];
__device__ float g_b3[16777216];

// ---- helpers ---------------------------------------------------------------

__device__ __forceinline__ uint32_t packbf(float a, float b) {
  __nv_bfloat162 t = __floats2bfloat162_rn(a, b);
  return *reinterpret_cast<uint32_t*>(&t);
}

// swizzled byte offset inside a 128x128 bf16 tile (row stride 256B, 16B granules)
__device__ __forceinline__ uint32_t swz(uint32_t row, uint32_t G) {
  return row * 256 + ((G ^ (row & 7)) << 4);
}

// hi/lo split of 8 floats -> two uint4 (8 bf16 each)
__device__ __forceinline__ void split8(const float* e, uint4& H, uint4& L) {
  uint32_t hw[4], lw[4];
#pragma unroll
  for (int q = 0; q < 4; ++q) {
    __nv_bfloat16 h0 = __float2bfloat16(e[2 * q]);
    __nv_bfloat16 h1 = __float2bfloat16(e[2 * q + 1]);
    float l0 = e[2 * q]     - __bfloat162float(h0);
    float l1 = e[2 * q + 1] - __bfloat162float(h1);
    hw[q] = ((uint32_t)__bfloat16_as_ushort(h1) << 16) | (uint32_t)__bfloat16_as_ushort(h0);
    lw[q] = packbf(l0, l1);
  }
  H = make_uint4(hw[0], hw[1], hw[2], hw[3]);
  L = make_uint4(lw[0], lw[1], lw[2], lw[3]);
}

// Stage global [128 rows][128 cols] (cols contiguous, row stride = gstride
// floats) into hi/lo tiles, smem layout [row][col].
__device__ __forceinline__ void stage_direct(char* sm, uint32_t offH, uint32_t offL,
                                             const float* __restrict__ g,
                                             long gstride, int tid) {
#pragma unroll
  for (int i = 0; i < 8; ++i) {
    int id = tid + i * TPB;
    int row = id >> 4, G = id & 15;
    const float4* p = reinterpret_cast<const float4*>(g + (long)row * gstride + G * 8);
    float4 x0 = p[0], x1 = p[1];
    float e[8] = {x0.x, x0.y, x0.z, x0.w, x1.x, x1.y, x1.z, x1.w};
    uint4 H, L;
    split8(e, H, L);
    uint32_t a = swz(row, G);
    *reinterpret_cast<uint4*>(sm + offH + a) = H;
    *reinterpret_cast<uint4*>(sm + offL + a) = L;
  }
}

// Stage global [128 k][128 n] (n contiguous) TRANSPOSED into smem [n][k].
__device__ __forceinline__ void stage_transpose(char* sm, uint32_t offH, uint32_t offL,
                                                const float* __restrict__ g,
                                                long gstride, int tid) {
#pragma unroll
  for (int i = 0; i < 8; ++i) {
    int id = tid + i * TPB;
    int G = id >> 7, n = id & 127;
    const float* p = g + (long)(8 * G) * gstride + n;
    float e[8];
#pragma unroll
    for (int j = 0; j < 8; ++j) e[j] = p[(long)j * gstride];
    uint4 H, L;
    split8(e, H, L);
    uint32_t a = swz(n, G);
    *reinterpret_cast<uint4*>(sm + offH + a) = H;
    *reinterpret_cast<uint4*>(sm + offL + a) = L;
  }
}

__device__ __forceinline__ void ldsm4(uint32_t& r0, uint32_t& r1, uint32_t& r2,
                                      uint32_t& r3, uint32_t addr) {
  asm volatile("ldmatrix.sync.aligned.m8n8.x4.shared.b16 {%0,%1,%2,%3}, [%4];"
               : "=r"(r0), "=r"(r1), "=r"(r2), "=r"(r3) : "r"(addr));
}

__device__ __forceinline__ void mma16816(float* c, uint32_t a0, uint32_t a1,
                                         uint32_t a2, uint32_t a3,
                                         uint32_t b0, uint32_t b1) {
  asm volatile("mma.sync.aligned.m16n8k16.row.col.f32.bf16.bf16.f32 "
               "{%0,%1,%2,%3}, {%4,%5,%6,%7}, {%8,%9}, {%0,%1,%2,%3};"
               : "+f"(c[0]), "+f"(c[1]), "+f"(c[2]), "+f"(c[3])
               : "r"(a0), "r"(a1), "r"(a2), "r"(a3), "r"(b0), "r"(b1));
}

__device__ __forceinline__ void zero_acc(float acc[16][4]) {
#pragma unroll
  for (int t = 0; t < 16; ++t)
#pragma unroll
    for (int q = 0; q < 4; ++q) acc[t][q] = 0.f;
}

// C[m][n] += sum_k A[m][k]*B^T[n][k], 128x128x128, warp wid owns rows 16*wid..+15.
__device__ __forceinline__ void mma_tile(uint32_t su, float acc[16][4], int lane, int wid) {
  const uint32_t l7 = lane & 7;
  uint32_t a_row = wid * 16 + (lane & 15);
  uint32_t aH = su + OFF_AH + a_row * 256;
  uint32_t aL = su + OFF_AL + a_row * 256;
  uint32_t a_gs = (lane >> 4) & 1;
  uint32_t b_row = (lane & 7) + ((lane >> 4) << 3);
  uint32_t bH = su + OFF_BH + b_row * 256;
  uint32_t bL = su + OFF_BL + b_row * 256;
  uint32_t b_gs = (lane >> 3) & 1;
#pragma unroll
  for (int ks = 0; ks < 8; ++ks) {
    uint32_t ao = ((2 * ks + a_gs) ^ l7) << 4;
    uint32_t ah0, ah1, ah2, ah3, al0, al1, al2, al3;
    ldsm4(ah0, ah1, ah2, ah3, aH + ao);
    ldsm4(al0, al1, al2, al3, aL + ao);
    uint32_t bo = ((2 * ks + b_gs) ^ l7) << 4;
#pragma unroll
    for (int jp = 0; jp < 8; ++jp) {
      uint32_t bh0, bh1, bh2, bh3, bl0, bl1, bl2, bl3;
      ldsm4(bh0, bh1, bh2, bh3, bH + jp * 4096 + bo);
      ldsm4(bl0, bl1, bl2, bl3, bL + jp * 4096 + bo);
      mma16816(acc[2 * jp],     ah0, ah1, ah2, ah3, bh0, bh1);
      mma16816(acc[2 * jp],     ah0, ah1, ah2, ah3, bl0, bl1);
      mma16816(acc[2 * jp],     al0, al1, al2, al3, bh0, bh1);
      mma16816(acc[2 * jp + 1], ah0, ah1, ah2, ah3, bh2, bh3);
      mma16816(acc[2 * jp + 1], ah0, ah1, ah2, ah3, bl2, bl3);
      mma16816(acc[2 * jp + 1], al0, al1, al2, al3, bh2, bh3);
    }
  }
}

__device__ __forceinline__ void store_tile(float* __restrict__ out, long rowStride,
                                           const float* __restrict__ bias, int biasBase,
                                           const float acc[16][4], int lane, int wid) {
  int g = lane >> 2, tk = lane & 3;
  int r0 = wid * 16 + g, r1 = r0 + 8;
  float b0v = bias ? bias[biasBase + r0] : 0.f;
  float b1v = bias ? bias[biasBase + r1] : 0.f;
#pragma unroll
  for (int j = 0; j < 16; ++j) {
    int col = j * 8 + tk * 2;
    float2 v0 = make_float2(acc[j][0] + b0v, acc[j][1] + b0v);
    float2 v1 = make_float2(acc[j][2] + b1v, acc[j][3] + b1v);
    *reinterpret_cast<float2*>(out + (long)r0 * rowStride + col) = v0;
    *reinterpret_cast<float2*>(out + (long)r1 * rowStride + col) = v1;
  }
}

// ---- kernel 1: resize  X[b,o,p] = Wr[o,:]·x[b,:,p] + br  (K=256) ----------
__global__ void __launch_bounds__(TPB, 1)
resize_kernel(const float* __restrict__ x, const float* __restrict__ Wr,
              const float* __restrict__ br) {
  extern __shared__ char sm[];
  uint32_t su = (uint32_t)__cvta_generic_to_shared(sm);
  int tid = threadIdx.x, lane = tid & 31, wid = tid >> 5;
  int pt = blockIdx.x, b = blockIdx.y;
  long p0 = (long)pt * 128;
  float acc[16][4];
  zero_acc(acc);
  for (int cc = 0; cc < 2; ++cc) {
    __syncthreads();
    stage_direct(sm, OFF_AH, OFF_AL, Wr + cc * 128, 256, tid);            // A[o][c]
    stage_transpose(sm, OFF_BH, OFF_BL,
                    x + (long)b * 4194304 + (long)cc * 2097152 + p0,
                    16384, tid);                                          // Bt[p][c] from x[c][p]
    __syncthreads();
    mma_tile(su, acc, lane, wid);
  }
  store_tile(g_b0 + (long)b * 2097152 + p0, 16384, br, 0, acc, lane, wid);
}

// ---- kernel 2/4: qkv projections ------------------------------------------
// width (height=0), per (b,r):  q[o][w] = sum_h W[o][h] X[h][w]   (Bt[w][h])
// height(height=1), per (b,c):  q[o][h] = sum_w W[o][w] M[h][w]   (Bt[h][w])
__global__ void __launch_bounds__(TPB, 1)
qkv_kernel(const float* __restrict__ Wq, const float* __restrict__ bq,
           const float* __restrict__ Wk, const float* __restrict__ bk,
           const float* __restrict__ Wv, const float* __restrict__ bv,
           int height) {
  extern __shared__ char sm[];
  uint32_t su = (uint32_t)__cvta_generic_to_shared(sm);
  int tid = threadIdx.x, lane = tid & 31, wid = tid >> 5;
  int rr = blockIdx.x, b = blockIdx.y;

  if (!height)
    stage_transpose(sm, OFF_BH, OFF_BL,
                    g_b0 + (long)b * 2097152 + (long)rr * 16384, 128, tid);
  else
    stage_direct(sm, OFF_BH, OFF_BL,
                 g_b0 + (long)b * 2097152 + (long)rr * 128, 16384, tid);

  const float* Ws[3] = {Wq, Wk, Wv};
  const float* bs[3] = {bq, bk, bv};
  float* outs[3] = {g_b1, g_b2, g_b3};
  long obase = (long)b * 2097152 + (long)rr * 128;

  for (int s = 0; s < 3; ++s) {
    __syncthreads();               // B visible (s==0) / prior mma done reading A
    stage_direct(sm, OFF_AH, OFF_AL, Ws[s], 128, tid);
    __syncthreads();
    float acc[16][4];
    zero_acc(acc);
    mma_tile(su, acc, lane, wid);
    store_tile(outs[s] + obase, 16384, bs[s], 0, acc, lane, wid);
  }
}

// ---- kernel 3/5: fused attention per (b,head) -----------------------------
__global__ void __launch_bounds__(TPB, 1)
attn_kernel() {
  extern __shared__ char sm[];
  uint32_t su = (uint32_t)__cvta_generic_to_shared(sm);
  int tid = threadIdx.x, lane = tid & 31, wid = tid >> 5;
  int o = blockIdx.x, b = blockIdx.y;
  long base = ((long)b * 128 + o) * 16384;

  stage_direct(sm, OFF_AH, OFF_AL, g_b1 + base, 128, tid);   // Q[r][w]
  stage_direct(sm, OFF_BH, OFF_BL, g_b2 + base, 128, tid);   // K[u][w]
  __syncthreads();

  float acc[16][4];
  zero_acc(acc);
  mma_tile(su, acc, lane, wid);        // S[r][u]
  __syncthreads();                     // everyone done reading tiles

  // row softmax (rows r0 = 16*wid + g, r1 = r0+8); P -> A tiles (layout [r][u])
  int g = lane >> 2, tk = lane & 3;
  float mx0 = -1e30f, mx1 = -1e30f;
#pragma unroll
  for (int j = 0; j < 16; ++j) {
    mx0 = fmaxf(mx0, fmaxf(acc[j][0], acc[j][1]));
    mx1 = fmaxf(mx1, fmaxf(acc[j][2], acc[j][3]));
  }
  mx0 = fmaxf(mx0, __shfl_xor_sync(0xffffffffu, mx0, 1));
  mx0 = fmaxf(mx0, __shfl_xor_sync(0xffffffffu, mx0, 2));
  mx1 = fmaxf(mx1, __shfl_xor_sync(0xffffffffu, mx1, 1));
  mx1 = fmaxf(mx1, __shfl_xor_sync(0xffffffffu, mx1, 2));
  float s0 = 0.f, s1 = 0.f;
#pragma unroll
  for (int j = 0; j < 16; ++j) {
    acc[j][0] = __expf(acc[j][0] - mx0); s0 += acc[j][0];
    acc[j][1] = __expf(acc[j][1] - mx0); s0 += acc[j][1];
    acc[j][2] = __expf(acc[j][2] - mx1); s1 += acc[j][2];
    acc[j][3] = __expf(acc[j][3] - mx1); s1 += acc[j][3];
  }
  s0 += __shfl_xor_sync(0xffffffffu, s0, 1);
  s0 += __shfl_xor_sync(0xffffffffu, s0, 2);
  s1 += __shfl_xor_sync(0xffffffffu, s1, 1);
  s1 += __shfl_xor_sync(0xffffffffu, s1, 2);
  float i0 = 1.f / s0, i1 = 1.f / s1;

  uint32_t r0 = wid * 16 + g, r1 = r0 + 8;
  uint32_t w0 = r0 * 256 + tk * 4, w1 = r1 * 256 + tk * 4;
#pragma unroll
  for (int j = 0; j < 16; ++j) {
    uint32_t off = (uint32_t)(j ^ g) << 4;
    float p00 = acc[j][0] * i0, p01 = acc[j][1] * i0;
    float p10 = acc[j][2] * i1, p11 = acc[j][3] * i1;
    __nv_bfloat16 h00 = __float2bfloat16(p00), h01 = __float2bfloat16(p01);
    __nv_bfloat16 h10 = __float2bfloat16(p10), h11 = __float2bfloat16(p11);
    uint32_t hw0 = ((uint32_t)__bfloat16_as_ushort(h01) << 16) | __bfloat16_as_ushort(h00);
    uint32_t hw1 = ((uint32_t)__bfloat16_as_ushort(h11) << 16) | __bfloat16_as_ushort(h10);
    uint32_t lw0 = packbf(p00 - __bfloat162float(h00), p01 - __bfloat162float(h01));
    uint32_t lw1 = packbf(p10 - __bfloat162float(h10), p11 - __bfloat162float(h11));
    *reinterpret_cast<uint32_t*>(sm + OFF_AH + w0 + off) = hw0;
    *reinterpret_cast<uint32_t*>(sm + OFF_AL + w0 + off) = lw0;
    *reinterpret_cast<uint32_t*>(sm + OFF_AH + w1 + off) = hw1;
    *reinterpret_cast<uint32_t*>(sm + OFF_AL + w1 + off) = lw1;
  }
  stage_transpose(sm, OFF_BH, OFF_BL, g_b3 + base, 128, tid);  // Bt[w][u] from V[u][w]
  __syncthreads();

  zero_acc(acc);
  mma_tile(su, acc, lane, wid);        // O[r][w] = P·V
  store_tile(g_b0 + base, 128, nullptr, 0, acc, lane, wid);
}

// ---- kernel 6: out2[b,w,c,h] -> hatT[b,p=(h,w)][c] ------------------------
__global__ void transpose_kernel() {
  __shared__ float tile[32][33];
  int bw = blockIdx.z;
  int b = bw >> 7, w = bw & 127;
  const float* s = g_b0 + ((long)b * 128 + w) * 16384;   // [c][h], h contiguous
  float* d = g_b1 + ((long)b << 21) + (long)w * 128;     // + h*16384 + c
  int c0 = blockIdx.x * 32, h0 = blockIdx.y * 32;
  for (int r = threadIdx.y; r < 32; r += 8)
    tile[r][threadIdx.x] = s[(long)(c0 + r) * 128 + h0 + threadIdx.x];
  __syncthreads();
  for (int r = threadIdx.y; r < 32; r += 8)
    d[(long)(h0 + r) * 16384 + c0 + threadIdx.x] = tile[threadIdx.x][r];
}

// ---- kernel 7: restore  Y[b,oc,p] = Wo[oc,:]·hatT[p,:] + bo ---------------
__global__ void __launch_bounds__(TPB, 1)
restore_kernel(const float* __restrict__ Wo, const float* __restrict__ bo,
               float* __restrict__ out) {
  extern __shared__ char sm[];
  uint32_t su = (uint32_t)__cvta_generic_to_shared(sm);
  int tid = threadIdx.x, lane = tid & 31, wid = tid >> 5;
  int pt = blockIdx.x, mh = blockIdx.y, b = blockIdx.z;
  long p0 = (long)pt * 128;

  stage_direct(sm, OFF_AH, OFF_AL, Wo + (long)mh * 16384, 128, tid);     // A[oc][c]
  stage_direct(sm, OFF_BH, OFF_BL, g_b1 + ((long)b << 21) + p0 * 128,
               128, tid);                                                // Bt[p][c]
  __syncthreads();

  float acc[16][4];
  zero_acc(acc);
  mma_tile(su, acc, lane, wid);
  store_tile(out + (long)b * 4194304 + (long)mh * 2097152 + p0, 16384,
             bo, mh * 128, acc, lane, wid);
}

// ---------------------------------------------------------------------------
extern "C" void kernel_launch(void* const* d_in, const int* in_sizes, int n_in,
                              void* d_out, int out_size) {
  (void)in_sizes; (void)n_in; (void)out_size;
  const float* x   = (const float*)d_in[0];
  const float* Wr  = (const float*)d_in[1];
  const float* br  = (const float*)d_in[2];
  const float* Wqw = (const float*)d_in[3];
  const float* bqw = (const float*)d_in[4];
  const float* Wkw = (const float*)d_in[5];
  const float* bkw = (const float*)d_in[6];
  const float* Wvw = (const float*)d_in[7];
  const float* bvw = (const float*)d_in[8];
  const float* Wqh = (const float*)d_in[9];
  const float* bqh = (const float*)d_in[10];
  const float* Wkh = (const float*)d_in[11];
  const float* bkh = (const float*)d_in[12];
  const float* Wvh = (const float*)d_in[13];
  const float* bvh = (const float*)d_in[14];
  const float* Wo  = (const float*)d_in[15];
  const float* bo  = (const float*)d_in[16];
  float* out = (float*)d_out;

  cudaFuncSetAttribute((const void*)resize_kernel,
                       cudaFuncAttributeMaxDynamicSharedMemorySize, SMEMB);
  cudaFuncSetAttribute((const void*)qkv_kernel,
                       cudaFuncAttributeMaxDynamicSharedMemorySize, SMEMB);
  cudaFuncSetAttribute((const void*)attn_kernel,
                       cudaFuncAttributeMaxDynamicSharedMemorySize, SMEMB);
  cudaFuncSetAttribute((const void*)restore_kernel,
                       cudaFuncAttributeMaxDynamicSharedMemorySize, SMEMB);

  resize_kernel<<<dim3(128, 8), TPB, SMEMB>>>(x, Wr, br);
  qkv_kernel<<<dim3(128, 8), TPB, SMEMB>>>(Wqw, bqw, Wkw, bkw, Wvw, bvw, 0);
  attn_kernel<<<dim3(128, 8), TPB, SMEMB>>>();
  qkv_kernel<<<dim3(128, 8), TPB, SMEMB>>>(Wqh, bqh, Wkh, bkh, Wvh, bvh, 1);
  attn_kernel<<<dim3(128, 8), TPB, SMEMB>>>();
  transpose_kernel<<<dim3(4, 4, 1024), dim3(32, 8)>>>();
  restore_kernel<<<dim3(128, 2, 8), TPB, SMEMB>>>(Wo, bo, out);
}